// round 1
// baseline (speedup 1.0000x reference)
#include <cuda_runtime.h>
#include <math.h>

#define DIM 1024
#define NHEADS 16
#define HD 64
#define LN_EPS 1e-5f

// Scratch (allocation-free rule: __device__ globals). 6 x 16MB = 96MB.
__device__ float g_qn[2 * 2048 * 1024];
__device__ float g_cn[2 * 2048 * 1024];
__device__ float g_Q [2 * 2048 * 1024];
__device__ float g_K [2 * 2048 * 1024];
__device__ float g_V [2 * 2048 * 1024];
__device__ float g_AO[2 * 2048 * 1024];

// ---------------------------------------------------------------------------
// LayerNorm: one block per row of 1024, 256 threads, 4 floats/thread.
// ---------------------------------------------------------------------------
__global__ void ln_kernel(const float* __restrict__ X, const float* __restrict__ g,
                          const float* __restrict__ b, float* __restrict__ Y) {
    __shared__ float red[2][8];
    int row = blockIdx.x;
    int tid = threadIdx.x;
    const float* x = X + (size_t)row * DIM;
    float4 v = *(const float4*)(x + tid * 4);
    float s  = v.x + v.y + v.z + v.w;
    float ss = v.x * v.x + v.y * v.y + v.z * v.z + v.w * v.w;
#pragma unroll
    for (int o = 16; o; o >>= 1) {
        s  += __shfl_xor_sync(0xffffffffu, s, o);
        ss += __shfl_xor_sync(0xffffffffu, ss, o);
    }
    if ((tid & 31) == 0) { red[0][tid >> 5] = s; red[1][tid >> 5] = ss; }
    __syncthreads();
    if (tid < 32) {
        float s2  = (tid < 8) ? red[0][tid] : 0.f;
        float ss2 = (tid < 8) ? red[1][tid] : 0.f;
#pragma unroll
        for (int o = 4; o; o >>= 1) {
            s2  += __shfl_xor_sync(0xffffffffu, s2, o);
            ss2 += __shfl_xor_sync(0xffffffffu, ss2, o);
        }
        if (tid == 0) { red[0][0] = s2; red[1][0] = ss2; }
    }
    __syncthreads();
    float mu  = red[0][0] * (1.f / DIM);
    float var = red[1][0] * (1.f / DIM) - mu * mu;
    float rstd = rsqrtf(var + LN_EPS);
    float4 gv = *(const float4*)(g + tid * 4);
    float4 bv = *(const float4*)(b + tid * 4);
    float4 o;
    o.x = (v.x - mu) * rstd * gv.x + bv.x;
    o.y = (v.y - mu) * rstd * gv.y + bv.y;
    o.z = (v.z - mu) * rstd * gv.z + bv.z;
    o.w = (v.w - mu) * rstd * gv.w + bv.w;
    *(float4*)(Y + (size_t)row * DIM + tid * 4) = o;
}

// ---------------------------------------------------------------------------
// SGEMM + bias (+ optional residual): C[M,N] = A[M,K] @ W[K,N] + bias (+ res)
// 128x128 block tile, BK=8, 256 threads, 8x8 microtile.
// ---------------------------------------------------------------------------
__global__ void __launch_bounds__(256, 2)
sgemm_bias(const float* __restrict__ A, const float* __restrict__ W,
           const float* __restrict__ bias, const float* __restrict__ res,
           float* __restrict__ C, int M, int N, int Kd) {
    __shared__ float As[8 * 132];  // [k][m], padded pitch 132 (16B-aligned rows)
    __shared__ float Bs[8 * 128];  // [k][n]
    int tid = threadIdx.x;
    int ty = tid >> 4, tx = tid & 15;
    int row0 = blockIdx.y * 128, col0 = blockIdx.x * 128;
    int arow = tid >> 1,  ak   = (tid & 1) * 4;
    int brow = tid >> 5,  bcol = (tid & 31) * 4;
    const float* Ap = A + (size_t)(row0 + arow) * Kd + ak;
    const float* Wp = W + (size_t)brow * N + col0 + bcol;

    float acc[8][8];
#pragma unroll
    for (int i = 0; i < 8; i++)
#pragma unroll
        for (int j = 0; j < 8; j++) acc[i][j] = 0.f;

    for (int k0 = 0; k0 < Kd; k0 += 8) {
        float4 a = *(const float4*)(Ap + k0);
        float4 w = *(const float4*)(Wp + (size_t)k0 * N);
        __syncthreads();
        As[(ak + 0) * 132 + arow] = a.x;
        As[(ak + 1) * 132 + arow] = a.y;
        As[(ak + 2) * 132 + arow] = a.z;
        As[(ak + 3) * 132 + arow] = a.w;
        *(float4*)(&Bs[brow * 128 + bcol]) = w;
        __syncthreads();
#pragma unroll
        for (int k = 0; k < 8; k++) {
            float af[8], bf[8];
            *(float4*)(af)     = *(const float4*)(&As[k * 132 + ty * 8]);
            *(float4*)(af + 4) = *(const float4*)(&As[k * 132 + ty * 8 + 4]);
            *(float4*)(bf)     = *(const float4*)(&Bs[k * 128 + tx * 8]);
            *(float4*)(bf + 4) = *(const float4*)(&Bs[k * 128 + tx * 8 + 4]);
#pragma unroll
            for (int i = 0; i < 8; i++)
#pragma unroll
                for (int j = 0; j < 8; j++) acc[i][j] += af[i] * bf[j];
        }
    }

#pragma unroll
    for (int i = 0; i < 8; i++) {
        int r = row0 + ty * 8 + i;
#pragma unroll
        for (int j4 = 0; j4 < 2; j4++) {
            int c = col0 + tx * 8 + j4 * 4;
            float4 bv = *(const float4*)(bias + c);
            float4 o;
            o.x = acc[i][j4 * 4 + 0] + bv.x;
            o.y = acc[i][j4 * 4 + 1] + bv.y;
            o.z = acc[i][j4 * 4 + 2] + bv.z;
            o.w = acc[i][j4 * 4 + 3] + bv.w;
            if (res) {
                float4 rv = *(const float4*)(res + (size_t)r * N + c);
                o.x += rv.x; o.y += rv.y; o.z += rv.z; o.w += rv.w;
            }
            *(float4*)(C + (size_t)r * N + c) = o;
        }
    }
}

// ---------------------------------------------------------------------------
// Flash attention: one block per (b, h, q-tile of 64). 256 threads (16x16),
// each thread owns a 4x4 fragment. K/V streamed in 64-key tiles via SMEM.
// Online softmax (scale 1/sqrt(64) = 0.125).
// ---------------------------------------------------------------------------
__global__ void __launch_bounds__(256, 3)
flash_kernel(const float* __restrict__ Q, const float* __restrict__ K,
             const float* __restrict__ V, float* __restrict__ O,
             int Nq, int Nc) {
    extern __shared__ float sm[];
    float* Qs = sm;              // [d][q] pitch 68 (transposed)
    float* Ks = Qs + 64 * 68;    // [d][k] pitch 68 (transposed)
    float* Vs = Ks + 64 * 68;    // [k][d] pitch 68
    float* Ps = Vs + 64 * 68;    // [q][k] pitch 68

    int tid = threadIdx.x;
    int ty = tid >> 4, tx = tid & 15;
    int bh = blockIdx.y;
    int b = bh >> 4, h = bh & 15;
    int q0 = blockIdx.x * 64;

    const float* Qg = Q + ((size_t)(b * Nq + q0)) * DIM + h * HD;
    const float* Kg = K + ((size_t)(b * Nc)) * DIM + h * HD;
    const float* Vg = V + ((size_t)(b * Nc)) * DIM + h * HD;

    // Load Q tile transposed: Qs[d][q]
#pragma unroll
    for (int i = 0; i < 4; i++) {
        int idx = tid + 256 * i;
        int r = idx >> 4, c4 = (idx & 15) * 4;
        float4 v = *(const float4*)(Qg + (size_t)r * DIM + c4);
        Qs[(c4 + 0) * 68 + r] = v.x;
        Qs[(c4 + 1) * 68 + r] = v.y;
        Qs[(c4 + 2) * 68 + r] = v.z;
        Qs[(c4 + 3) * 68 + r] = v.w;
    }

    float m[4], l[4], acc[16];
#pragma unroll
    for (int i = 0; i < 4; i++) { m[i] = -1e30f; l[i] = 0.f; }
#pragma unroll
    for (int i = 0; i < 16; i++) acc[i] = 0.f;

    for (int kt = 0; kt < Nc; kt += 64) {
        __syncthreads();  // previous iteration (and Qs load) complete
        // Load K tile transposed + V tile direct
#pragma unroll
        for (int i = 0; i < 4; i++) {
            int idx = tid + 256 * i;
            int r = idx >> 4, c4 = (idx & 15) * 4;
            float4 kv = *(const float4*)(Kg + (size_t)(kt + r) * DIM + c4);
            Ks[(c4 + 0) * 68 + r] = kv.x;
            Ks[(c4 + 1) * 68 + r] = kv.y;
            Ks[(c4 + 2) * 68 + r] = kv.z;
            Ks[(c4 + 3) * 68 + r] = kv.w;
            float4 vv = *(const float4*)(Vg + (size_t)(kt + r) * DIM + c4);
            *(float4*)(&Vs[r * 68 + c4]) = vv;
        }
        __syncthreads();

        // S fragment: s[i][j] = Q[q0+ty*4+i] . K[kt+tx*4+j]
        float s[4][4];
#pragma unroll
        for (int i = 0; i < 4; i++)
#pragma unroll
            for (int j = 0; j < 4; j++) s[i][j] = 0.f;

#pragma unroll 16
        for (int d = 0; d < 64; d++) {
            float4 qf = *(const float4*)(&Qs[d * 68 + ty * 4]);
            float4 kf = *(const float4*)(&Ks[d * 68 + tx * 4]);
            s[0][0] += qf.x * kf.x; s[0][1] += qf.x * kf.y; s[0][2] += qf.x * kf.z; s[0][3] += qf.x * kf.w;
            s[1][0] += qf.y * kf.x; s[1][1] += qf.y * kf.y; s[1][2] += qf.y * kf.z; s[1][3] += qf.y * kf.w;
            s[2][0] += qf.z * kf.x; s[2][1] += qf.z * kf.y; s[2][2] += qf.z * kf.z; s[2][3] += qf.z * kf.w;
            s[3][0] += qf.w * kf.x; s[3][1] += qf.w * kf.y; s[3][2] += qf.w * kf.z; s[3][3] += qf.w * kf.w;
        }

        // Online softmax per q-row (row group = 16 lanes sharing ty)
#pragma unroll
        for (int i = 0; i < 4; i++) {
#pragma unroll
            for (int j = 0; j < 4; j++) s[i][j] *= 0.125f;
            float rm = fmaxf(fmaxf(s[i][0], s[i][1]), fmaxf(s[i][2], s[i][3]));
#pragma unroll
            for (int o = 8; o; o >>= 1) rm = fmaxf(rm, __shfl_xor_sync(0xffffffffu, rm, o, 16));
            float mnew = fmaxf(m[i], rm);
            float corr = __expf(m[i] - mnew);
            float rs = 0.f;
#pragma unroll
            for (int j = 0; j < 4; j++) { s[i][j] = __expf(s[i][j] - mnew); rs += s[i][j]; }
#pragma unroll
            for (int o = 8; o; o >>= 1) rs += __shfl_xor_sync(0xffffffffu, rs, o, 16);
            l[i] = l[i] * corr + rs;
            m[i] = mnew;
            acc[i * 4 + 0] *= corr; acc[i * 4 + 1] *= corr;
            acc[i * 4 + 2] *= corr; acc[i * 4 + 3] *= corr;
            *(float4*)(&Ps[(ty * 4 + i) * 68 + tx * 4]) =
                make_float4(s[i][0], s[i][1], s[i][2], s[i][3]);
        }
        __syncthreads();

        // acc += P @ V  (64 k-steps)
#pragma unroll 16
        for (int kk = 0; kk < 64; kk++) {
            float p0 = Ps[(ty * 4 + 0) * 68 + kk];
            float p1 = Ps[(ty * 4 + 1) * 68 + kk];
            float p2 = Ps[(ty * 4 + 2) * 68 + kk];
            float p3 = Ps[(ty * 4 + 3) * 68 + kk];
            float4 vf = *(const float4*)(&Vs[kk * 68 + tx * 4]);
            acc[0]  += p0 * vf.x; acc[1]  += p0 * vf.y; acc[2]  += p0 * vf.z; acc[3]  += p0 * vf.w;
            acc[4]  += p1 * vf.x; acc[5]  += p1 * vf.y; acc[6]  += p1 * vf.z; acc[7]  += p1 * vf.w;
            acc[8]  += p2 * vf.x; acc[9]  += p2 * vf.y; acc[10] += p2 * vf.z; acc[11] += p2 * vf.w;
            acc[12] += p3 * vf.x; acc[13] += p3 * vf.y; acc[14] += p3 * vf.z; acc[15] += p3 * vf.w;
        }
    }

#pragma unroll
    for (int i = 0; i < 4; i++) {
        float invl = 1.f / l[i];
        float4 o = make_float4(acc[i * 4 + 0] * invl, acc[i * 4 + 1] * invl,
                               acc[i * 4 + 2] * invl, acc[i * 4 + 3] * invl);
        *(float4*)(O + ((size_t)(b * Nq + q0 + ty * 4 + i)) * DIM + h * HD + tx * 4) = o;
    }
}

// ---------------------------------------------------------------------------
extern "C" void kernel_launch(void* const* d_in, const int* in_sizes, int n_in,
                              void* d_out, int out_size) {
    const float* query   = (const float*)d_in[0];
    const float* context = (const float*)d_in[1];
    const float* Wq = (const float*)d_in[2];
    const float* bq = (const float*)d_in[3];
    const float* Wk = (const float*)d_in[4];
    const float* bk = (const float*)d_in[5];
    const float* Wv = (const float*)d_in[6];
    const float* bv = (const float*)d_in[7];
    const float* Wo = (const float*)d_in[8];
    const float* bo = (const float*)d_in[9];
    const float* gq     = (const float*)d_in[10];
    const float* betaq  = (const float*)d_in[11];
    const float* gkv    = (const float*)d_in[12];
    const float* betakv = (const float*)d_in[13];
    float* out = (float*)d_out;

    const int B = 2, Nq = 2048, Nc = 2048;
    const int Mq = B * Nq, Mc = B * Nc;

    float *qn, *cn, *Qp, *Kp, *Vp, *AO;
    cudaGetSymbolAddress((void**)&qn, g_qn);
    cudaGetSymbolAddress((void**)&cn, g_cn);
    cudaGetSymbolAddress((void**)&Qp, g_Q);
    cudaGetSymbolAddress((void**)&Kp, g_K);
    cudaGetSymbolAddress((void**)&Vp, g_V);
    cudaGetSymbolAddress((void**)&AO, g_AO);

    ln_kernel<<<Mq, 256>>>(query,   gq,  betaq,  qn);
    ln_kernel<<<Mc, 256>>>(context, gkv, betakv, cn);

    dim3 gg(DIM / 128, Mq / 128);
    sgemm_bias<<<gg, 256>>>(qn, Wq, bq, nullptr, Qp, Mq, DIM, DIM);
    sgemm_bias<<<gg, 256>>>(cn, Wk, bk, nullptr, Kp, Mc, DIM, DIM);
    sgemm_bias<<<gg, 256>>>(cn, Wv, bv, nullptr, Vp, Mc, DIM, DIM);

    size_t shmem = (size_t)4 * 64 * 68 * sizeof(float);  // 69,632 B
    cudaFuncSetAttribute(flash_kernel, cudaFuncAttributeMaxDynamicSharedMemorySize, (int)shmem);
    dim3 gf(Nq / 64, B * NHEADS);
    flash_kernel<<<gf, 256, shmem>>>(Qp, Kp, Vp, AO, Nq, Nc);

    sgemm_bias<<<gg, 256>>>(AO, Wo, bo, query, out, Mq, DIM, DIM);
}

// round 3
// speedup vs baseline: 6.0221x; 6.0221x over previous
#include <cuda_runtime.h>
#include <cuda_bf16.h>
#include <math.h>
#include <stdint.h>

#define DIM 1024
#define LN_EPS 1e-5f

// ---------------------------------------------------------------------------
// Scratch (__device__ globals; allocation-free rule)
// ---------------------------------------------------------------------------
__device__ __align__(16) __nv_bfloat16 g_qn[4096 * 1024];
__device__ __align__(16) __nv_bfloat16 g_cn[4096 * 1024];
__device__ __align__(16) __nv_bfloat16 g_wt[4][1024 * 1024];
__device__ __align__(16) __nv_bfloat16 g_Qb[4096 * 1024];
__device__ __align__(16) __nv_bfloat16 g_Kb[4096 * 1024];
__device__ __align__(16) __nv_bfloat16 g_Vb[4096 * 1024];
__device__ __align__(16) __nv_bfloat16 g_AO[4096 * 1024];

// ---------------------------------------------------------------------------
// Helpers (sm_80-level: mma.sync bf16, ldmatrix, cp.async)
// ---------------------------------------------------------------------------
__device__ __forceinline__ uint32_t smem_u32(const void* p) {
    uint32_t a;
    asm("{ .reg .u64 t; cvta.to.shared.u64 t, %1; cvt.u32.u64 %0, t; }" : "=r"(a) : "l"(p));
    return a;
}
#define CP16(s, g) asm volatile("cp.async.cg.shared.global [%0], [%1], 16;" :: "r"(s), "l"(g))
#define CPCOMMIT() asm volatile("cp.async.commit_group;" ::: "memory")
#define CPWAIT(n)  asm volatile("cp.async.wait_group %0;" :: "n"(n) : "memory")

__device__ __forceinline__ void ldsm4(uint32_t* r, uint32_t addr) {
    asm volatile("ldmatrix.sync.aligned.m8n8.x4.shared.b16 {%0,%1,%2,%3}, [%4];"
                 : "=r"(r[0]), "=r"(r[1]), "=r"(r[2]), "=r"(r[3]) : "r"(addr));
}
__device__ __forceinline__ void ldsm4t(uint32_t* r, uint32_t addr) {
    asm volatile("ldmatrix.sync.aligned.m8n8.x4.trans.shared.b16 {%0,%1,%2,%3}, [%4];"
                 : "=r"(r[0]), "=r"(r[1]), "=r"(r[2]), "=r"(r[3]) : "r"(addr));
}
__device__ __forceinline__ void mma_bf16(float* c, const uint32_t* a, const uint32_t* b) {
    asm volatile(
        "mma.sync.aligned.m16n8k16.row.col.f32.bf16.bf16.f32 "
        "{%0,%1,%2,%3}, {%4,%5,%6,%7}, {%8,%9}, {%0,%1,%2,%3};"
        : "+f"(c[0]), "+f"(c[1]), "+f"(c[2]), "+f"(c[3])
        : "r"(a[0]), "r"(a[1]), "r"(a[2]), "r"(a[3]), "r"(b[0]), "r"(b[1]));
}
__device__ __forceinline__ uint32_t packbf(float x, float y) {
    __nv_bfloat162 h = __floats2bfloat162_rn(x, y);
    return *reinterpret_cast<uint32_t*>(&h);
}

#define SWZ64(o)  ((o) ^ (((o) >> 3) & 0x30))
#define SWZ128(o) ((o) ^ (((o) >> 3) & 0x70))

// exp(0.125*d) for d <= 0, FMA-pipe only (no MUFU), ~4e-5 rel err
__device__ __forceinline__ float fexp125(float d) {
    d = fmaxf(d, -600.0f);
    float t = fmaf(d, 0.18033688f, 12582912.0f);   // 0.125*log2(e), + 1.5*2^23
    float r = t - 12582912.0f;
    float f = fmaf(d, 0.18033688f, -r);            // frac in [-0.5, 0.5]
    int   e = __float_as_int(t) - 0x4B400000;      // rint(d*0.125*log2e)
    float p = fmaf(0.00961812f, f, 0.05550411f);
    p = fmaf(p, f, 0.24022651f);
    p = fmaf(p, f, 0.69314718f);
    p = fmaf(p, f, 1.0f);
    return __int_as_float(__float_as_int(p) + (e << 23));
}

// ---------------------------------------------------------------------------
// LayerNorm -> bf16
// ---------------------------------------------------------------------------
__global__ void ln_bf16(const float* __restrict__ X, const float* __restrict__ g,
                        const float* __restrict__ b, __nv_bfloat16* __restrict__ Y) {
    __shared__ float red[2][8];
    int row = blockIdx.x, tid = threadIdx.x;
    float4 v = *(const float4*)(X + (size_t)row * DIM + tid * 4);
    float s  = v.x + v.y + v.z + v.w;
    float ss = v.x * v.x + v.y * v.y + v.z * v.z + v.w * v.w;
#pragma unroll
    for (int o = 16; o; o >>= 1) {
        s  += __shfl_xor_sync(0xffffffffu, s, o);
        ss += __shfl_xor_sync(0xffffffffu, ss, o);
    }
    if ((tid & 31) == 0) { red[0][tid >> 5] = s; red[1][tid >> 5] = ss; }
    __syncthreads();
    if (tid < 32) {
        float s2  = (tid < 8) ? red[0][tid] : 0.f;
        float ss2 = (tid < 8) ? red[1][tid] : 0.f;
#pragma unroll
        for (int o = 4; o; o >>= 1) {
            s2  += __shfl_xor_sync(0xffffffffu, s2, o);
            ss2 += __shfl_xor_sync(0xffffffffu, ss2, o);
        }
        if (tid == 0) { red[0][0] = s2; red[1][0] = ss2; }
    }
    __syncthreads();
    float mu  = red[0][0] * (1.f / DIM);
    float var = red[1][0] * (1.f / DIM) - mu * mu;
    float rstd = rsqrtf(var + LN_EPS);
    float4 gv = *(const float4*)(g + tid * 4);
    float4 bv = *(const float4*)(b + tid * 4);
    float o0 = (v.x - mu) * rstd * gv.x + bv.x;
    float o1 = (v.y - mu) * rstd * gv.y + bv.y;
    float o2 = (v.z - mu) * rstd * gv.z + bv.z;
    float o3 = (v.w - mu) * rstd * gv.w + bv.w;
    size_t base = (size_t)row * DIM + tid * 4;
    *(uint32_t*)(Y + base)     = packbf(o0, o1);
    *(uint32_t*)(Y + base + 2) = packbf(o2, o3);
}

// ---------------------------------------------------------------------------
// Weight transpose: W[K][N] fp32 -> T[N][K] bf16
// ---------------------------------------------------------------------------
__global__ void wt_bf16(const float* __restrict__ W, __nv_bfloat16* __restrict__ T) {
    __shared__ float t[32][33];
    int n0 = blockIdx.x * 32, k0 = blockIdx.y * 32;
    int tx = threadIdx.x, ty = threadIdx.y;  // 32 x 8
#pragma unroll
    for (int i = 0; i < 32; i += 8)
        t[ty + i][tx] = W[(size_t)(k0 + ty + i) * DIM + n0 + tx];
    __syncthreads();
#pragma unroll
    for (int i = 0; i < 32; i += 8)
        T[(size_t)(n0 + ty + i) * DIM + k0 + tx] = __float2bfloat16(t[tx][ty + i]);
}

// ---------------------------------------------------------------------------
// bf16 tensor-core GEMM: C[4096,1024] = A[4096,1024] @ Bt^T  (Bt is [N][K])
// block tile 128x128, BK=32, 8 warps (64x32 warp tiles), 3-stage cp.async.
// Epilogue: +bias, output bf16 (Cb) or fp32+residual (Cf).
// ---------------------------------------------------------------------------
__global__ void __launch_bounds__(256)
gemm_mma(const __nv_bfloat16* __restrict__ A, const __nv_bfloat16* __restrict__ Bt,
         const float* __restrict__ bias, const float* __restrict__ res,
         __nv_bfloat16* __restrict__ Cb, float* __restrict__ Cf) {
    extern __shared__ char smc[];
    uint32_t sb = smem_u32(smc);
    const int tid = threadIdx.x;
    const int l = tid & 31, wid = tid >> 5;
    const int row0 = blockIdx.y * 128, col0 = blockIdx.x * 128;
    const int wm = (wid >> 2) * 64, wn = (wid & 3) * 32;

    // cp.async addressing: 512 16B-chunks per 128x32 tile, 2 per thread
    const int lrow = tid >> 2, lc = tid & 3;
    const char* Ag = (const char*)(A  + (size_t)(row0 + lrow) * DIM + lc * 8);
    const char* Bg = (const char*)(Bt + (size_t)(col0 + lrow) * DIM + lc * 8);
    const uint32_t sO0 = SWZ64((uint32_t)(lrow * 64 + lc * 16));
    const uint32_t sO1 = SWZ64((uint32_t)((lrow + 64) * 64 + lc * 16));

#define G_LOADSTAGE(kt, s) do {                                   \
        uint32_t _b = sb + (s) * 16384;                           \
        const char* _a = Ag + (size_t)(kt) * 64;                  \
        const char* _w = Bg + (size_t)(kt) * 64;                  \
        CP16(_b + sO0, _a);                                       \
        CP16(_b + sO1, _a + (size_t)64 * 2048);                   \
        CP16(_b + 8192 + sO0, _w);                                \
        CP16(_b + 8192 + sO1, _w + (size_t)64 * 2048);            \
    } while (0)

    // fragment smem offsets (stage-relative)
    uint32_t offA[4][2], offB[2][2];
#pragma unroll
    for (int mt = 0; mt < 4; mt++)
#pragma unroll
        for (int k16 = 0; k16 < 2; k16++)
            offA[mt][k16] = SWZ64((uint32_t)((wm + mt * 16 + (l & 15)) * 64 + k16 * 32 + (l >> 4) * 16));
#pragma unroll
    for (int np = 0; np < 2; np++)
#pragma unroll
        for (int k16 = 0; k16 < 2; k16++)
            offB[np][k16] = 8192u + SWZ64((uint32_t)((wn + np * 16 + (l & 7) + ((l >> 4) << 3)) * 64 +
                                                     k16 * 32 + ((l >> 3) & 1) * 16));

    float c[4][4][4];
#pragma unroll
    for (int i = 0; i < 4; i++)
#pragma unroll
        for (int j = 0; j < 4; j++)
#pragma unroll
            for (int q = 0; q < 4; q++) c[i][j][q] = 0.f;

    G_LOADSTAGE(0, 0); CPCOMMIT();
    G_LOADSTAGE(1, 1); CPCOMMIT();
    G_LOADSTAGE(2, 2); CPCOMMIT();

    for (int kt = 0; kt < 32; kt++) {
        if (kt < 30) { CPWAIT(2); } else if (kt < 31) { CPWAIT(1); } else { CPWAIT(0); }
        __syncthreads();
        uint32_t base = sb + (kt % 3) * 16384;
#pragma unroll
        for (int k16 = 0; k16 < 2; k16++) {
            uint32_t a[4][4], b[2][4];
#pragma unroll
            for (int mt = 0; mt < 4; mt++) ldsm4(a[mt], base + offA[mt][k16]);
#pragma unroll
            for (int np = 0; np < 2; np++) ldsm4(b[np], base + offB[np][k16]);
#pragma unroll
            for (int mt = 0; mt < 4; mt++)
#pragma unroll
                for (int nt = 0; nt < 4; nt++)
                    mma_bf16(c[mt][nt], a[mt], &b[nt >> 1][(nt & 1) * 2]);
        }
        __syncthreads();
        if (kt + 3 < 32) { G_LOADSTAGE(kt + 3, kt % 3); CPCOMMIT(); }
    }

    // epilogue
    const int g = l >> 2, t = l & 3;
#pragma unroll
    for (int mt = 0; mt < 4; mt++) {
        int r0 = row0 + wm + mt * 16 + g;
#pragma unroll
        for (int nt = 0; nt < 4; nt++) {
            int cc = col0 + wn + nt * 8 + t * 2;
            float b0 = bias[cc], b1 = bias[cc + 1];
            float v0 = c[mt][nt][0] + b0, v1 = c[mt][nt][1] + b1;
            float v2 = c[mt][nt][2] + b0, v3 = c[mt][nt][3] + b1;
            if (Cf) {
                float2 q0 = *(const float2*)(res + (size_t)r0 * DIM + cc);
                float2 q1 = *(const float2*)(res + (size_t)(r0 + 8) * DIM + cc);
                *(float2*)(Cf + (size_t)r0 * DIM + cc)       = make_float2(v0 + q0.x, v1 + q0.y);
                *(float2*)(Cf + (size_t)(r0 + 8) * DIM + cc) = make_float2(v2 + q1.x, v3 + q1.y);
            } else {
                *(uint32_t*)(Cb + (size_t)r0 * DIM + cc)       = packbf(v0, v1);
                *(uint32_t*)(Cb + (size_t)(r0 + 8) * DIM + cc) = packbf(v2, v3);
            }
        }
    }
#undef G_LOADSTAGE
}

// ---------------------------------------------------------------------------
// Flash attention, bf16 tensor cores. Block = 128 thr (4 warps), q-tile 64,
// key chunks of 64, double-buffered cp.async, FMA-pipe exp, bf16 output.
// ---------------------------------------------------------------------------
__global__ void __launch_bounds__(128)
flash_mma(const __nv_bfloat16* __restrict__ Q, const __nv_bfloat16* __restrict__ K,
          const __nv_bfloat16* __restrict__ V, __nv_bfloat16* __restrict__ O) {
    extern __shared__ char smc[];
    uint32_t sb = smem_u32(smc);   // Qs @0 (8KB), Ks @8192+s*8192, Vs @24576+s*8192
    const int tid = threadIdx.x;
    const int l = tid & 31, wid = tid >> 5;
    const int bb = blockIdx.y >> 4, h = blockIdx.y & 15;
    const int q0 = blockIdx.x * 64;

    // cp.async addressing: 64 rows x 8 chunks = 512 chunks, 4 per thread
    const int frow = tid >> 3, fc = tid & 7;
    const char* Qg = (const char*)(Q + (size_t)(bb * 2048 + q0 + frow) * DIM + h * 64 + fc * 8);
    const char* Kg = (const char*)(K + (size_t)(bb * 2048 + frow) * DIM + h * 64 + fc * 8);
    const char* Vg = (const char*)(V + (size_t)(bb * 2048 + frow) * DIM + h * 64 + fc * 8);
    uint32_t sOf[4];
#pragma unroll
    for (int j = 0; j < 4; j++) sOf[j] = SWZ128((uint32_t)((frow + 16 * j) * 128 + fc * 16));

#define F_LOADKV(kt, s) do {                                                     \
        uint32_t _bk = sb + 8192 + (s) * 8192;                                   \
        uint32_t _bv = sb + 24576 + (s) * 8192;                                  \
        size_t _go = ((size_t)(kt) * 64) * 2048;                                 \
        _Pragma("unroll")                                                        \
        for (int _j = 0; _j < 4; _j++) {                                         \
            CP16(_bk + sOf[_j], Kg + _go + (size_t)(16 * _j) * 2048);            \
            CP16(_bv + sOf[_j], Vg + _go + (size_t)(16 * _j) * 2048);            \
        }                                                                        \
    } while (0)

    // prologue: group0 = Q + chunk0, group1 = chunk1
#pragma unroll
    for (int j = 0; j < 4; j++) CP16(sb + sOf[j], Qg + (size_t)(16 * j) * 2048);
    F_LOADKV(0, 0); CPCOMMIT();
    F_LOADKV(1, 1); CPCOMMIT();

    // fragment smem offsets
    uint32_t offQ[4], offK[4][4], offV[4][4];
#pragma unroll
    for (int k16 = 0; k16 < 4; k16++)
        offQ[k16] = SWZ128((uint32_t)((wid * 16 + (l & 15)) * 128 + k16 * 32 + (l >> 4) * 16));
#pragma unroll
    for (int np = 0; np < 4; np++)
#pragma unroll
        for (int k16 = 0; k16 < 4; k16++)
            offK[np][k16] = SWZ128((uint32_t)((np * 16 + (l & 7) + ((l >> 4) << 3)) * 128 +
                                              k16 * 32 + ((l >> 3) & 1) * 16));
#pragma unroll
    for (int np = 0; np < 4; np++)
#pragma unroll
        for (int kk = 0; kk < 4; kk++)
            offV[np][kk] = SWZ128((uint32_t)((kk * 16 + (l & 15)) * 128 + np * 32 + (l >> 4) * 16));

    uint32_t qf[4][4];
    float o[8][4];
#pragma unroll
    for (int i = 0; i < 8; i++)
#pragma unroll
        for (int j = 0; j < 4; j++) o[i][j] = 0.f;
    float m0 = -1e30f, m1 = -1e30f, l0 = 0.f, l1 = 0.f;

    for (int c = 0; c < 32; c++) {
        if (c < 31) { CPWAIT(1); } else { CPWAIT(0); }
        __syncthreads();
        if (c == 0) {
#pragma unroll
            for (int k16 = 0; k16 < 4; k16++) ldsm4(qf[k16], sb + offQ[k16]);
        }
        uint32_t kbase = sb + 8192 + (c & 1) * 8192;
        uint32_t vbase = sb + 24576 + (c & 1) * 8192;

        // S = Q @ K^T (raw scores; scale folded into exp)
        float sv[8][4];
#pragma unroll
        for (int i = 0; i < 8; i++)
#pragma unroll
            for (int j = 0; j < 4; j++) sv[i][j] = 0.f;
#pragma unroll
        for (int k16 = 0; k16 < 4; k16++) {
#pragma unroll
            for (int np = 0; np < 4; np++) {
                uint32_t kb[4];
                ldsm4(kb, kbase + offK[np][k16]);
                mma_bf16(sv[2 * np],     qf[k16], &kb[0]);
                mma_bf16(sv[2 * np + 1], qf[k16], &kb[2]);
            }
        }

        // online softmax (rows g and g+8 of this warp's 16 q-rows)
        float mx0 = -1e30f, mx1 = -1e30f;
#pragma unroll
        for (int nt = 0; nt < 8; nt++) {
            mx0 = fmaxf(mx0, fmaxf(sv[nt][0], sv[nt][1]));
            mx1 = fmaxf(mx1, fmaxf(sv[nt][2], sv[nt][3]));
        }
        mx0 = fmaxf(mx0, __shfl_xor_sync(0xffffffffu, mx0, 1));
        mx0 = fmaxf(mx0, __shfl_xor_sync(0xffffffffu, mx0, 2));
        mx1 = fmaxf(mx1, __shfl_xor_sync(0xffffffffu, mx1, 1));
        mx1 = fmaxf(mx1, __shfl_xor_sync(0xffffffffu, mx1, 2));
        float mn0 = fmaxf(m0, mx0), mn1 = fmaxf(m1, mx1);
        float corr0 = fexp125(m0 - mn0), corr1 = fexp125(m1 - mn1);
        m0 = mn0; m1 = mn1;
        float rs0 = 0.f, rs1 = 0.f;
#pragma unroll
        for (int nt = 0; nt < 8; nt++) {
            sv[nt][0] = fexp125(sv[nt][0] - mn0); rs0 += sv[nt][0];
            sv[nt][1] = fexp125(sv[nt][1] - mn0); rs0 += sv[nt][1];
            sv[nt][2] = fexp125(sv[nt][2] - mn1); rs1 += sv[nt][2];
            sv[nt][3] = fexp125(sv[nt][3] - mn1); rs1 += sv[nt][3];
        }
        rs0 += __shfl_xor_sync(0xffffffffu, rs0, 1);
        rs0 += __shfl_xor_sync(0xffffffffu, rs0, 2);
        rs1 += __shfl_xor_sync(0xffffffffu, rs1, 1);
        rs1 += __shfl_xor_sync(0xffffffffu, rs1, 2);
        l0 = l0 * corr0 + rs0;
        l1 = l1 * corr1 + rs1;
#pragma unroll
        for (int dt = 0; dt < 8; dt++) {
            o[dt][0] *= corr0; o[dt][1] *= corr0;
            o[dt][2] *= corr1; o[dt][3] *= corr1;
        }

        // O += P @ V
#pragma unroll
        for (int kk = 0; kk < 4; kk++) {
            uint32_t ap[4];
            ap[0] = packbf(sv[2 * kk][0],     sv[2 * kk][1]);
            ap[1] = packbf(sv[2 * kk][2],     sv[2 * kk][3]);
            ap[2] = packbf(sv[2 * kk + 1][0], sv[2 * kk + 1][1]);
            ap[3] = packbf(sv[2 * kk + 1][2], sv[2 * kk + 1][3]);
#pragma unroll
            for (int np = 0; np < 4; np++) {
                uint32_t vb[4];
                ldsm4t(vb, vbase + offV[np][kk]);
                mma_bf16(o[2 * np],     ap, &vb[0]);
                mma_bf16(o[2 * np + 1], ap, &vb[2]);
            }
        }

        __syncthreads();
        if (c + 2 < 32) { F_LOADKV(c + 2, c & 1); CPCOMMIT(); }
    }

    // normalize + store bf16
    const int g = l >> 2, t = l & 3;
    float il0 = 1.f / l0, il1 = 1.f / l1;
    size_t r0 = (size_t)(bb * 2048 + q0 + wid * 16 + g) * DIM + h * 64;
    size_t r1 = r0 + 8 * DIM;
#pragma unroll
    for (int dt = 0; dt < 8; dt++) {
        int cc = dt * 8 + t * 2;
        *(uint32_t*)(O + r0 + cc) = packbf(o[dt][0] * il0, o[dt][1] * il0);
        *(uint32_t*)(O + r1 + cc) = packbf(o[dt][2] * il1, o[dt][3] * il1);
    }
#undef F_LOADKV
}

// ---------------------------------------------------------------------------
extern "C" void kernel_launch(void* const* d_in, const int* in_sizes, int n_in,
                              void* d_out, int out_size) {
    const float* query   = (const float*)d_in[0];
    const float* context = (const float*)d_in[1];
    const float* Wq = (const float*)d_in[2];
    const float* bq = (const float*)d_in[3];
    const float* Wk = (const float*)d_in[4];
    const float* bk = (const float*)d_in[5];
    const float* Wv = (const float*)d_in[6];
    const float* bv = (const float*)d_in[7];
    const float* Wo = (const float*)d_in[8];
    const float* bo = (const float*)d_in[9];
    const float* gq     = (const float*)d_in[10];
    const float* betaq  = (const float*)d_in[11];
    const float* gkv    = (const float*)d_in[12];
    const float* betakv = (const float*)d_in[13];
    float* out = (float*)d_out;

    __nv_bfloat16 *qn, *cn, *wt, *Qb, *Kb, *Vb, *AO;
    cudaGetSymbolAddress((void**)&qn, g_qn);
    cudaGetSymbolAddress((void**)&cn, g_cn);
    cudaGetSymbolAddress((void**)&wt, g_wt);
    cudaGetSymbolAddress((void**)&Qb, g_Qb);
    cudaGetSymbolAddress((void**)&Kb, g_Kb);
    cudaGetSymbolAddress((void**)&Vb, g_Vb);
    cudaGetSymbolAddress((void**)&AO, g_AO);
    __nv_bfloat16* wts[4] = {wt, wt + 1024 * 1024, wt + 2 * 1024 * 1024, wt + 3 * 1024 * 1024};

    const int GEMM_SMEM  = 3 * 16384;  // 48KB
    const int FLASH_SMEM = 40960;
    cudaFuncSetAttribute(gemm_mma,  cudaFuncAttributeMaxDynamicSharedMemorySize, GEMM_SMEM);
    cudaFuncSetAttribute(flash_mma, cudaFuncAttributeMaxDynamicSharedMemorySize, FLASH_SMEM);

    // LayerNorms -> bf16
    ln_bf16<<<4096, 256>>>(query,   gq,  betaq,  qn);
    ln_bf16<<<4096, 256>>>(context, gkv, betakv, cn);

    // weight transposes
    dim3 wtg(32, 32), wtb(32, 8);
    wt_bf16<<<wtg, wtb>>>(Wq, wts[0]);
    wt_bf16<<<wtg, wtb>>>(Wk, wts[1]);
    wt_bf16<<<wtg, wtb>>>(Wv, wts[2]);
    wt_bf16<<<wtg, wtb>>>(Wo, wts[3]);

    // projections (tensor cores)
    dim3 gg(8, 32);
    gemm_mma<<<gg, 256, GEMM_SMEM>>>(qn, wts[0], bq, nullptr, Qb, nullptr);
    gemm_mma<<<gg, 256, GEMM_SMEM>>>(cn, wts[1], bk, nullptr, Kb, nullptr);
    gemm_mma<<<gg, 256, GEMM_SMEM>>>(cn, wts[2], bv, nullptr, Vb, nullptr);

    // flash attention (tensor cores)
    dim3 gf(32, 32);
    flash_mma<<<gf, 128, FLASH_SMEM>>>(Qb, Kb, Vb, AO);

    // O projection + bias + residual -> fp32 out
    gemm_mma<<<gg, 256, GEMM_SMEM>>>(AO, wts[3], bo, query, nullptr, out);
}

// round 4
// speedup vs baseline: 7.0792x; 1.1755x over previous
#include <cuda_runtime.h>
#include <cuda_bf16.h>
#include <math.h>
#include <stdint.h>

#define DIM 1024
#define LN_EPS 1e-5f
#define QSCALE 0.18033688011112042f   // 0.125 * log2(e)

// ---------------------------------------------------------------------------
// Scratch (__device__ globals; allocation-free rule)
// ---------------------------------------------------------------------------
__device__ __align__(16) __nv_bfloat16 g_qn[4096 * 1024];
__device__ __align__(16) __nv_bfloat16 g_cn[4096 * 1024];
__device__ __align__(16) __nv_bfloat16 g_wt[4][1024 * 1024];
__device__ __align__(16) __nv_bfloat16 g_Qb[4096 * 1024];
__device__ __align__(16) __nv_bfloat16 g_Kb[4096 * 1024];
__device__ __align__(16) __nv_bfloat16 g_Vb[4096 * 1024];
__device__ __align__(16) __nv_bfloat16 g_AO[4096 * 1024];

// ---------------------------------------------------------------------------
// Helpers
// ---------------------------------------------------------------------------
__device__ __forceinline__ uint32_t smem_u32(const void* p) {
    uint32_t a;
    asm("{ .reg .u64 t; cvta.to.shared.u64 t, %1; cvt.u32.u64 %0, t; }" : "=r"(a) : "l"(p));
    return a;
}
#define CP16(s, g) asm volatile("cp.async.cg.shared.global [%0], [%1], 16;" :: "r"(s), "l"(g))
#define CPCOMMIT() asm volatile("cp.async.commit_group;" ::: "memory")
#define CPWAIT(n)  asm volatile("cp.async.wait_group %0;" :: "n"(n) : "memory")

__device__ __forceinline__ void ldsm4(uint32_t* r, uint32_t addr) {
    asm volatile("ldmatrix.sync.aligned.m8n8.x4.shared.b16 {%0,%1,%2,%3}, [%4];"
                 : "=r"(r[0]), "=r"(r[1]), "=r"(r[2]), "=r"(r[3]) : "r"(addr));
}
__device__ __forceinline__ void ldsm4t(uint32_t* r, uint32_t addr) {
    asm volatile("ldmatrix.sync.aligned.m8n8.x4.trans.shared.b16 {%0,%1,%2,%3}, [%4];"
                 : "=r"(r[0]), "=r"(r[1]), "=r"(r[2]), "=r"(r[3]) : "r"(addr));
}
__device__ __forceinline__ void mma_bf16(float* c, const uint32_t* a, const uint32_t* b) {
    asm volatile(
        "mma.sync.aligned.m16n8k16.row.col.f32.bf16.bf16.f32 "
        "{%0,%1,%2,%3}, {%4,%5,%6,%7}, {%8,%9}, {%0,%1,%2,%3};"
        : "+f"(c[0]), "+f"(c[1]), "+f"(c[2]), "+f"(c[3])
        : "r"(a[0]), "r"(a[1]), "r"(a[2]), "r"(a[3]), "r"(b[0]), "r"(b[1]));
}
__device__ __forceinline__ uint32_t packbf(float x, float y) {
    __nv_bfloat162 h = __floats2bfloat162_rn(x, y);
    return *reinterpret_cast<uint32_t*>(&h);
}
// MUFU exp2 (scale pre-folded into Q, so softmax = ex2(s - m))
__device__ __forceinline__ float ex2a(float x) {
    float r;
    asm("ex2.approx.ftz.f32 %0, %1;" : "=f"(r) : "f"(x));
    return r;
}

#define SWZ64(o)  ((o) ^ (((o) >> 3) & 0x30))
#define SWZ128(o) ((o) ^ (((o) >> 3) & 0x70))

// ---------------------------------------------------------------------------
// LayerNorm -> bf16
// ---------------------------------------------------------------------------
__global__ void ln_bf16(const float* __restrict__ X, const float* __restrict__ g,
                        const float* __restrict__ b, __nv_bfloat16* __restrict__ Y) {
    __shared__ float red[2][8];
    int row = blockIdx.x, tid = threadIdx.x;
    float4 v = *(const float4*)(X + (size_t)row * DIM + tid * 4);
    float s  = v.x + v.y + v.z + v.w;
    float ss = v.x * v.x + v.y * v.y + v.z * v.z + v.w * v.w;
#pragma unroll
    for (int o = 16; o; o >>= 1) {
        s  += __shfl_xor_sync(0xffffffffu, s, o);
        ss += __shfl_xor_sync(0xffffffffu, ss, o);
    }
    if ((tid & 31) == 0) { red[0][tid >> 5] = s; red[1][tid >> 5] = ss; }
    __syncthreads();
    if (tid < 32) {
        float s2  = (tid < 8) ? red[0][tid] : 0.f;
        float ss2 = (tid < 8) ? red[1][tid] : 0.f;
#pragma unroll
        for (int o = 4; o; o >>= 1) {
            s2  += __shfl_xor_sync(0xffffffffu, s2, o);
            ss2 += __shfl_xor_sync(0xffffffffu, ss2, o);
        }
        if (tid == 0) { red[0][0] = s2; red[1][0] = ss2; }
    }
    __syncthreads();
    float mu  = red[0][0] * (1.f / DIM);
    float var = red[1][0] * (1.f / DIM) - mu * mu;
    float rstd = rsqrtf(var + LN_EPS);
    float4 gv = *(const float4*)(g + tid * 4);
    float4 bv = *(const float4*)(b + tid * 4);
    float o0 = (v.x - mu) * rstd * gv.x + bv.x;
    float o1 = (v.y - mu) * rstd * gv.y + bv.y;
    float o2 = (v.z - mu) * rstd * gv.z + bv.z;
    float o3 = (v.w - mu) * rstd * gv.w + bv.w;
    size_t base = (size_t)row * DIM + tid * 4;
    *(uint32_t*)(Y + base)     = packbf(o0, o1);
    *(uint32_t*)(Y + base + 2) = packbf(o2, o3);
}

// ---------------------------------------------------------------------------
// All-4-weights fp32 -> bf16 convert, layout preserved [K][N]
// ---------------------------------------------------------------------------
__global__ void wconv(const float* __restrict__ W0, const float* __restrict__ W1,
                      const float* __restrict__ W2, const float* __restrict__ W3,
                      __nv_bfloat16* __restrict__ dst) {
    int idx = blockIdx.x * blockDim.x + threadIdx.x;  // float4 index, 4 x 262144
    int which = idx >> 18;
    int off = (idx & 262143) * 4;
    const float* src = (which == 0) ? W0 : (which == 1) ? W1 : (which == 2) ? W2 : W3;
    float4 v = *(const float4*)(src + off);
    __nv_bfloat16* d = dst + (size_t)which * (1024 * 1024) + off;
    *(uint32_t*)(d)     = packbf(v.x, v.y);
    *(uint32_t*)(d + 2) = packbf(v.z, v.w);
}

// ---------------------------------------------------------------------------
// bf16 tensor-core GEMM: C[4096,1024] = A[4096,1024] @ W  (W is bf16 [K][N])
// block tile 128x128, BK=32, 8 warps (64x32 warp tiles), 3-stage cp.async.
// B operand consumed via ldmatrix.trans straight from [K][N] layout.
// Epilogue: (+bias)*scale -> bf16 (Cb), or +bias+residual -> fp32 (Cf).
// ---------------------------------------------------------------------------
__global__ void __launch_bounds__(256)
gemm_mma(const __nv_bfloat16* __restrict__ A, const __nv_bfloat16* __restrict__ W,
         const float* __restrict__ bias, const float* __restrict__ res,
         __nv_bfloat16* __restrict__ Cb, float* __restrict__ Cf, float scale) {
    extern __shared__ char smc[];
    uint32_t sb = smem_u32(smc);
    const int tid = threadIdx.x;
    const int l = tid & 31, wid = tid >> 5;
    const int row0 = blockIdx.y * 128, col0 = blockIdx.x * 128;
    const int wm = (wid >> 2) * 64, wn = (wid & 3) * 32;

    // A loader: 128 rows x 64B (SWZ64), 2 chunks/thread
    const int lrow = tid >> 2, lc = tid & 3;
    const char* Ag = (const char*)(A + (size_t)(row0 + lrow) * DIM + lc * 8);
    const uint32_t sA0 = SWZ64((uint32_t)(lrow * 64 + lc * 16));
    const uint32_t sA1 = SWZ64((uint32_t)((lrow + 64) * 64 + lc * 16));
    // B loader: 32 rows (k) x 256B (n), swizzle col^=(row&15)<<4, 2 chunks/thread
    const int brow = tid >> 4, bcg = (tid & 15) * 16;
    const uint32_t sB0 = 8192u + (uint32_t)(brow * 256) + (uint32_t)(bcg ^ (brow << 4));
    const uint32_t sB1 = sB0 + 16 * 256;
    const char* Bg = (const char*)(W + (size_t)brow * DIM + col0 + (tid & 15) * 8);

#define G_LOADSTAGE(kt, s) do {                                   \
        uint32_t _b = sb + (s) * 16384;                           \
        const char* _a = Ag + (size_t)(kt) * 64;                  \
        const char* _w = Bg + (size_t)(kt) * (32 * 2048);         \
        CP16(_b + sA0, _a);                                       \
        CP16(_b + sA1, _a + (size_t)64 * 2048);                   \
        CP16(_b + sB0, _w);                                       \
        CP16(_b + sB1, _w + (size_t)16 * 2048);                   \
    } while (0)

    // fragment smem offsets (stage-relative)
    uint32_t offA[4][2], offB[2][2];
#pragma unroll
    for (int mt = 0; mt < 4; mt++)
#pragma unroll
        for (int k16 = 0; k16 < 2; k16++)
            offA[mt][k16] = SWZ64((uint32_t)((wm + mt * 16 + (l & 15)) * 64 + k16 * 32 + (l >> 4) * 16));
#pragma unroll
    for (int np = 0; np < 2; np++)
#pragma unroll
        for (int k16 = 0; k16 < 2; k16++) {
            int r = k16 * 16 + (l & 15);
            int cbyte = wn * 2 + np * 32 + (l >> 4) * 16;
            offB[np][k16] = 8192u + (uint32_t)(r * 256) + (uint32_t)(cbyte ^ ((r & 15) << 4));
        }

    float c[4][4][4];
#pragma unroll
    for (int i = 0; i < 4; i++)
#pragma unroll
        for (int j = 0; j < 4; j++)
#pragma unroll
            for (int q = 0; q < 4; q++) c[i][j][q] = 0.f;

    G_LOADSTAGE(0, 0); CPCOMMIT();
    G_LOADSTAGE(1, 1); CPCOMMIT();
    G_LOADSTAGE(2, 2); CPCOMMIT();

    for (int kt = 0; kt < 32; kt++) {
        if (kt < 30) { CPWAIT(2); } else if (kt < 31) { CPWAIT(1); } else { CPWAIT(0); }
        __syncthreads();
        uint32_t base = sb + (kt % 3) * 16384;
#pragma unroll
        for (int k16 = 0; k16 < 2; k16++) {
            uint32_t a[4][4], b[2][4];
#pragma unroll
            for (int mt = 0; mt < 4; mt++) ldsm4(a[mt], base + offA[mt][k16]);
#pragma unroll
            for (int np = 0; np < 2; np++) ldsm4t(b[np], base + offB[np][k16]);
#pragma unroll
            for (int mt = 0; mt < 4; mt++)
#pragma unroll
                for (int nt = 0; nt < 4; nt++)
                    mma_bf16(c[mt][nt], a[mt], &b[nt >> 1][(nt & 1) * 2]);
        }
        __syncthreads();
        if (kt + 3 < 32) { G_LOADSTAGE(kt + 3, kt % 3); CPCOMMIT(); }
    }

    // epilogue
    const int g = l >> 2, t = l & 3;
#pragma unroll
    for (int mt = 0; mt < 4; mt++) {
        int r0 = row0 + wm + mt * 16 + g;
#pragma unroll
        for (int nt = 0; nt < 4; nt++) {
            int cc = col0 + wn + nt * 8 + t * 2;
            float b0 = bias[cc], b1 = bias[cc + 1];
            float v0 = (c[mt][nt][0] + b0) * scale, v1 = (c[mt][nt][1] + b1) * scale;
            float v2 = (c[mt][nt][2] + b0) * scale, v3 = (c[mt][nt][3] + b1) * scale;
            if (Cf) {
                float2 q0 = *(const float2*)(res + (size_t)r0 * DIM + cc);
                float2 q1 = *(const float2*)(res + (size_t)(r0 + 8) * DIM + cc);
                *(float2*)(Cf + (size_t)r0 * DIM + cc)       = make_float2(v0 + q0.x, v1 + q0.y);
                *(float2*)(Cf + (size_t)(r0 + 8) * DIM + cc) = make_float2(v2 + q1.x, v3 + q1.y);
            } else {
                *(uint32_t*)(Cb + (size_t)r0 * DIM + cc)       = packbf(v0, v1);
                *(uint32_t*)(Cb + (size_t)(r0 + 8) * DIM + cc) = packbf(v2, v3);
            }
        }
    }
#undef G_LOADSTAGE
}

// ---------------------------------------------------------------------------
// Flash attention, bf16 tensor cores. 256 thr (8 warps), q-tile 128,
// key chunks of 64, double-buffered cp.async, MUFU ex2 softmax (Q pre-scaled).
// ---------------------------------------------------------------------------
__global__ void __launch_bounds__(256)
flash_mma(const __nv_bfloat16* __restrict__ Q, const __nv_bfloat16* __restrict__ K,
          const __nv_bfloat16* __restrict__ V, __nv_bfloat16* __restrict__ O) {
    extern __shared__ char smc[];
    uint32_t sb = smem_u32(smc);   // Q @0 (16KB), K @16384+s*8192, V @32768+s*8192
    const int tid = threadIdx.x;
    const int l = tid & 31, wid = tid >> 5;
    const int bb = blockIdx.y >> 4, h = blockIdx.y & 15;
    const int q0 = blockIdx.x * 128;

    // K/V loader: 64 rows x 8 granules, 2/thread
    const int frow = tid >> 3, fc = tid & 7;
    const char* Kg = (const char*)(K + (size_t)(bb * 2048 + frow) * DIM + h * 64 + fc * 8);
    const char* Vg = (const char*)(V + (size_t)(bb * 2048 + frow) * DIM + h * 64 + fc * 8);
    const uint32_t sKV0 = SWZ128((uint32_t)(frow * 128 + fc * 16));
    const uint32_t sKV1 = SWZ128((uint32_t)((frow + 32) * 128 + fc * 16));

#define F_LOADKV(kt, s) do {                                                     \
        uint32_t _bk = sb + 16384 + (s) * 8192;                                  \
        uint32_t _bv = sb + 32768 + (s) * 8192;                                  \
        size_t _go = ((size_t)(kt) * 64) * 2048;                                 \
        CP16(_bk + sKV0, Kg + _go);                                              \
        CP16(_bk + sKV1, Kg + _go + (size_t)32 * 2048);                          \
        CP16(_bv + sKV0, Vg + _go);                                              \
        CP16(_bv + sKV1, Vg + _go + (size_t)32 * 2048);                          \
    } while (0)

    // prologue: Q tile (128 rows x 128B, 4 granules/thread) + KV chunks 0,1
#pragma unroll
    for (int j = 0; j < 4; j++) {
        int gidx = tid + 256 * j;
        int r = gidx >> 3, cb = (gidx & 7) * 16;
        CP16(sb + SWZ128((uint32_t)(r * 128 + cb)),
             (const char*)(Q + (size_t)(bb * 2048 + q0 + r) * DIM + h * 64) + cb);
    }
    F_LOADKV(0, 0); CPCOMMIT();
    F_LOADKV(1, 1); CPCOMMIT();

    // fragment smem offsets
    uint32_t offQ[4], offK[4][4], offV[4][4];
#pragma unroll
    for (int k16 = 0; k16 < 4; k16++)
        offQ[k16] = SWZ128((uint32_t)((wid * 16 + (l & 15)) * 128 + k16 * 32 + (l >> 4) * 16));
#pragma unroll
    for (int np = 0; np < 4; np++)
#pragma unroll
        for (int k16 = 0; k16 < 4; k16++)
            offK[np][k16] = SWZ128((uint32_t)((np * 16 + (l & 7) + ((l >> 4) << 3)) * 128 +
                                              k16 * 32 + ((l >> 3) & 1) * 16));
#pragma unroll
    for (int np = 0; np < 4; np++)
#pragma unroll
        for (int kk = 0; kk < 4; kk++)
            offV[np][kk] = SWZ128((uint32_t)((kk * 16 + (l & 15)) * 128 + np * 32 + (l >> 4) * 16));

    uint32_t qf[4][4];
    float o[8][4];
#pragma unroll
    for (int i = 0; i < 8; i++)
#pragma unroll
        for (int j = 0; j < 4; j++) o[i][j] = 0.f;
    float m0 = -1e30f, m1 = -1e30f, l0 = 0.f, l1 = 0.f;

    for (int c = 0; c < 32; c++) {
        if (c < 31) { CPWAIT(1); } else { CPWAIT(0); }
        __syncthreads();
        if (c == 0) {
#pragma unroll
            for (int k16 = 0; k16 < 4; k16++) ldsm4(qf[k16], sb + offQ[k16]);
        }
        uint32_t kbase = sb + 16384 + (c & 1) * 8192;
        uint32_t vbase = sb + 32768 + (c & 1) * 8192;

        // S = Q' @ K^T (Q pre-scaled by 0.125*log2e)
        float sv[8][4];
#pragma unroll
        for (int i = 0; i < 8; i++)
#pragma unroll
            for (int j = 0; j < 4; j++) sv[i][j] = 0.f;
#pragma unroll
        for (int k16 = 0; k16 < 4; k16++) {
#pragma unroll
            for (int np = 0; np < 4; np++) {
                uint32_t kb[4];
                ldsm4(kb, kbase + offK[np][k16]);
                mma_bf16(sv[2 * np],     qf[k16], &kb[0]);
                mma_bf16(sv[2 * np + 1], qf[k16], &kb[2]);
            }
        }

        // online softmax in log2 domain: p = exp2(s - m), MUFU only
        float mx0 = -1e30f, mx1 = -1e30f;
#pragma unroll
        for (int nt = 0; nt < 8; nt++) {
            mx0 = fmaxf(mx0, fmaxf(sv[nt][0], sv[nt][1]));
            mx1 = fmaxf(mx1, fmaxf(sv[nt][2], sv[nt][3]));
        }
        mx0 = fmaxf(mx0, __shfl_xor_sync(0xffffffffu, mx0, 1));
        mx0 = fmaxf(mx0, __shfl_xor_sync(0xffffffffu, mx0, 2));
        mx1 = fmaxf(mx1, __shfl_xor_sync(0xffffffffu, mx1, 1));
        mx1 = fmaxf(mx1, __shfl_xor_sync(0xffffffffu, mx1, 2));
        float mn0 = fmaxf(m0, mx0), mn1 = fmaxf(m1, mx1);
        float corr0 = ex2a(m0 - mn0), corr1 = ex2a(m1 - mn1);
        m0 = mn0; m1 = mn1;
        float rs0 = 0.f, rs1 = 0.f;
#pragma unroll
        for (int nt = 0; nt < 8; nt++) {
            sv[nt][0] = ex2a(sv[nt][0] - mn0); rs0 += sv[nt][0];
            sv[nt][1] = ex2a(sv[nt][1] - mn0); rs0 += sv[nt][1];
            sv[nt][2] = ex2a(sv[nt][2] - mn1); rs1 += sv[nt][2];
            sv[nt][3] = ex2a(sv[nt][3] - mn1); rs1 += sv[nt][3];
        }
        rs0 += __shfl_xor_sync(0xffffffffu, rs0, 1);
        rs0 += __shfl_xor_sync(0xffffffffu, rs0, 2);
        rs1 += __shfl_xor_sync(0xffffffffu, rs1, 1);
        rs1 += __shfl_xor_sync(0xffffffffu, rs1, 2);
        l0 = l0 * corr0 + rs0;
        l1 = l1 * corr1 + rs1;
#pragma unroll
        for (int dt = 0; dt < 8; dt++) {
            o[dt][0] *= corr0; o[dt][1] *= corr0;
            o[dt][2] *= corr1; o[dt][3] *= corr1;
        }

        // O += P @ V
#pragma unroll
        for (int kk = 0; kk < 4; kk++) {
            uint32_t ap[4];
            ap[0] = packbf(sv[2 * kk][0],     sv[2 * kk][1]);
            ap[1] = packbf(sv[2 * kk][2],     sv[2 * kk][3]);
            ap[2] = packbf(sv[2 * kk + 1][0], sv[2 * kk + 1][1]);
            ap[3] = packbf(sv[2 * kk + 1][2], sv[2 * kk + 1][3]);
#pragma unroll
            for (int np = 0; np < 4; np++) {
                uint32_t vb[4];
                ldsm4t(vb, vbase + offV[np][kk]);
                mma_bf16(o[2 * np],     ap, &vb[0]);
                mma_bf16(o[2 * np + 1], ap, &vb[2]);
            }
        }

        __syncthreads();
        if (c + 2 < 32) { F_LOADKV(c + 2, c & 1); CPCOMMIT(); }
    }

    // normalize + store bf16
    const int g = l >> 2, t = l & 3;
    float il0 = 1.f / l0, il1 = 1.f / l1;
    size_t r0 = (size_t)(bb * 2048 + q0 + wid * 16 + g) * DIM + h * 64;
    size_t r1 = r0 + 8 * DIM;
#pragma unroll
    for (int dt = 0; dt < 8; dt++) {
        int cc = dt * 8 + t * 2;
        *(uint32_t*)(O + r0 + cc) = packbf(o[dt][0] * il0, o[dt][1] * il0);
        *(uint32_t*)(O + r1 + cc) = packbf(o[dt][2] * il1, o[dt][3] * il1);
    }
#undef F_LOADKV
}

// ---------------------------------------------------------------------------
extern "C" void kernel_launch(void* const* d_in, const int* in_sizes, int n_in,
                              void* d_out, int out_size) {
    const float* query   = (const float*)d_in[0];
    const float* context = (const float*)d_in[1];
    const float* Wq = (const float*)d_in[2];
    const float* bq = (const float*)d_in[3];
    const float* Wk = (const float*)d_in[4];
    const float* bk = (const float*)d_in[5];
    const float* Wv = (const float*)d_in[6];
    const float* bv = (const float*)d_in[7];
    const float* Wo = (const float*)d_in[8];
    const float* bo = (const float*)d_in[9];
    const float* gq     = (const float*)d_in[10];
    const float* betaq  = (const float*)d_in[11];
    const float* gkv    = (const float*)d_in[12];
    const float* betakv = (const float*)d_in[13];
    float* out = (float*)d_out;

    __nv_bfloat16 *qn, *cn, *wt, *Qb, *Kb, *Vb, *AO;
    cudaGetSymbolAddress((void**)&qn, g_qn);
    cudaGetSymbolAddress((void**)&cn, g_cn);
    cudaGetSymbolAddress((void**)&wt, g_wt);
    cudaGetSymbolAddress((void**)&Qb, g_Qb);
    cudaGetSymbolAddress((void**)&Kb, g_Kb);
    cudaGetSymbolAddress((void**)&Vb, g_Vb);
    cudaGetSymbolAddress((void**)&AO, g_AO);
    __nv_bfloat16* wts[4] = {wt, wt + 1024 * 1024, wt + 2 * 1024 * 1024, wt + 3 * 1024 * 1024};

    const int GEMM_SMEM  = 3 * 16384;  // 48KB
    const int FLASH_SMEM = 49152;      // 16KB Q + 2x8KB K + 2x8KB V
    cudaFuncSetAttribute(gemm_mma,  cudaFuncAttributeMaxDynamicSharedMemorySize, GEMM_SMEM);
    cudaFuncSetAttribute(flash_mma, cudaFuncAttributeMaxDynamicSharedMemorySize, FLASH_SMEM);

    // LayerNorms -> bf16
    ln_bf16<<<4096, 256>>>(query,   gq,  betaq,  qn);
    ln_bf16<<<4096, 256>>>(context, gkv, betakv, cn);

    // all weights fp32 -> bf16 (layout preserved)
    wconv<<<4096, 256>>>(Wq, Wk, Wv, Wo, wt);

    // projections (tensor cores). Q pre-scaled by 0.125*log2(e).
    dim3 gg(8, 32);
    gemm_mma<<<gg, 256, GEMM_SMEM>>>(qn, wts[0], bq, nullptr, Qb, nullptr, QSCALE);
    gemm_mma<<<gg, 256, GEMM_SMEM>>>(cn, wts[1], bk, nullptr, Kb, nullptr, 1.0f);
    gemm_mma<<<gg, 256, GEMM_SMEM>>>(cn, wts[2], bv, nullptr, Vb, nullptr, 1.0f);

    // flash attention (tensor cores, MUFU softmax)
    dim3 gf(16, 32);
    flash_mma<<<gf, 256, FLASH_SMEM>>>(Qb, Kb, Vb, AO);

    // O projection + bias + residual -> fp32 out
    gemm_mma<<<gg, 256, GEMM_SMEM>>>(AO, wts[3], bo, query, nullptr, out, 1.0f);
}